// round 4
// baseline (speedup 1.0000x reference)
#include <cuda_runtime.h>

// Problem constants (T=4, B=1, C=256, N=1024, H=16, D=16)
#define T_   4
#define C_   256
#define N_   1024
#define M_   4          // T*B
#define H_   16
#define D_   16
#define CN   (C_*N_)    // 262144
#define TOT  (M_*C_*N_) // 1048576
#define EPSV 1e-5f

// ---------------- scratch (device globals; allocation-free) ----------------
__device__ float    g_h[3][TOT];      // q/k/v pre-BN activations (12 MiB)
__device__ float    g_p[TOT];         // proj pre-BN activations (4 MiB)
__device__ float    g_s2[TOT];        // attn-lif output as {0,1} fp32 (4 MiB)
__device__ float    g_mean[4*C_];     // per-channel mean  (z=0..2 branches, z=3 proj)
__device__ float    g_istd[4*C_];     // per-channel 1/sqrt(var+eps)
__device__ unsigned g_bits[3][M_*H_*N_]; // bitpacked spikes: mask over d at (t,h,n)

// ---------------- GEMM body: O[m,o,n] = sum_c W[o,c] * X[m,c,n] -------------
// BM=BN=64, BK=16, 256 threads, 4x4 register tile per thread.
__device__ __forceinline__ void gemm_body(const float* __restrict__ W,
                                          const float* __restrict__ X,
                                          float* __restrict__ O)
{
    __shared__ float As[16][68];   // [k][o], padded (272B rows: 16B aligned, low conflict)
    __shared__ float Bs[16][64];   // [k][n]

    const int tid     = threadIdx.x;
    const int colTile = blockIdx.x;          // 0..63  (4096 cols / 64)
    const int m       = colTile >> 4;        // 64 cols always inside one m (64 | 1024)
    const int n0      = (colTile & 15) << 6;
    const int o0      = blockIdx.y << 6;     // 0..3 row tiles
    const int ty      = tid >> 4;
    const int tx      = tid & 15;

    float acc[4][4] = {};

    for (int k0 = 0; k0 < C_; k0 += 16) {
        #pragma unroll
        for (int i = tid; i < 64 * 16; i += 256) {   // 4 iters
            int o_ = i >> 4, c_ = i & 15;
            As[c_][o_] = W[(o0 + o_) * C_ + k0 + c_];
        }
        #pragma unroll
        for (int i = tid; i < 16 * 64; i += 256) {   // 4 iters
            int c_ = i >> 6, n_ = i & 63;
            Bs[c_][n_] = X[m * CN + (k0 + c_) * N_ + n0 + n_];
        }
        __syncthreads();

        #pragma unroll
        for (int k = 0; k < 16; ++k) {
            float a[4], b[4];
            #pragma unroll
            for (int i = 0; i < 4; ++i) a[i] = As[k][ty * 4 + i];
            #pragma unroll
            for (int j = 0; j < 4; ++j) b[j] = Bs[k][tx * 4 + j];
            #pragma unroll
            for (int i = 0; i < 4; ++i)
                #pragma unroll
                for (int j = 0; j < 4; ++j)
                    acc[i][j] += a[i] * b[j];
        }
        __syncthreads();
    }

    #pragma unroll
    for (int i = 0; i < 4; ++i)
        #pragma unroll
        for (int j = 0; j < 4; ++j)
            O[m * CN + (o0 + ty * 4 + i) * N_ + n0 + tx * 4 + j] = acc[i][j];
}

// Branch GEMMs: z=0 -> Wq@x, z=1 -> Wk@y, z=2 -> Wv@y
__global__ void __launch_bounds__(256)
gemm_branch(const float* __restrict__ x, const float* __restrict__ y,
            const float* __restrict__ Wq, const float* __restrict__ Wk,
            const float* __restrict__ Wv)
{
    const int z = blockIdx.z;
    const float* W = (z == 0) ? Wq : (z == 1) ? Wk : Wv;
    const float* X = (z == 0) ? x : y;
    gemm_body(W, X, g_h[z]);
}

// Proj GEMM: g_p = Wp @ g_s2
__global__ void __launch_bounds__(256)
gemm_proj(const float* __restrict__ Wp)
{
    gemm_body(Wp, g_s2, g_p);
}

// ---------------- per-channel BN stats over (m,n): 4096 samples -------------
// mode 0: branches (grid (C_,3)), mode 1: proj (grid (C_,1))
__global__ void __launch_bounds__(256)
stats_kernel(int mode)
{
    const int c = blockIdx.x;
    const int z = blockIdx.y;
    const float* Hs;
    int sidx;
    if (mode == 0) { Hs = g_h[z]; sidx = z * C_ + c; }
    else           { Hs = g_p;    sidx = 3 * C_ + c; }

    const int tid = threadIdx.x;
    float s = 0.0f, q = 0.0f;
    #pragma unroll
    for (int j = 0; j < 16; ++j) {
        int idx = tid + j * 256;         // 0..4095
        int m = idx >> 10, n = idx & 1023;
        float v = Hs[m * CN + c * N_ + n];
        s += v;
        q += v * v;
    }
    #pragma unroll
    for (int off = 16; off > 0; off >>= 1) {
        s += __shfl_down_sync(0xFFFFFFFFu, s, off);
        q += __shfl_down_sync(0xFFFFFFFFu, q, off);
    }
    __shared__ float ss[8], qq[8];
    const int wid = tid >> 5, lane = tid & 31;
    if (lane == 0) { ss[wid] = s; qq[wid] = q; }
    __syncthreads();
    if (tid == 0) {
        float st = 0.0f, qt = 0.0f;
        #pragma unroll
        for (int w = 0; w < 8; ++w) { st += ss[w]; qt += qq[w]; }
        float mean = st * (1.0f / 4096.0f);
        float var  = qt * (1.0f / 4096.0f) - mean * mean;
        g_mean[sidx] = mean;
        g_istd[sidx] = rsqrtf(var + EPSV);
    }
}

// ---------------- BN + LIF spike + bitpack (vth = 1.0) ----------------------
__global__ void __launch_bounds__(256)
pack_kernel(const float* __restrict__ gq, const float* __restrict__ bq,
            const float* __restrict__ gk, const float* __restrict__ bk,
            const float* __restrict__ gv, const float* __restrict__ bv)
{
    const int z   = blockIdx.y;
    const int idx = blockIdx.x * 256 + threadIdx.x;  // (m,h,n), n fastest; 65536 total
    const int n = idx & 1023;
    const int h = (idx >> 10) & 15;
    const int m = idx >> 14;
    const float* G  = (z == 0) ? gq : (z == 1) ? gk : gv;
    const float* Bt = (z == 0) ? bq : (z == 1) ? bk : bv;
    const float* Hs = g_h[z];

    unsigned mask = 0;
    #pragma unroll
    for (int d = 0; d < 16; ++d) {
        int c = h * 16 + d;
        float xv = Hs[m * CN + c * N_ + n];
        float bn = G[c] * (xv - g_mean[z * C_ + c]) * g_istd[z * C_ + c] + Bt[c];
        if (bn >= 1.0f) mask |= (1u << d);
    }
    g_bits[z][idx] = mask;
}

// ---------------- attention: out = q (k^T v); exact integer path ------------
// One block per (t,h). G[d1][d2] = sum_n k[n,d1]*v[n,d2] (ints, <=1024).
// s2[n,d] = ( sum_{d1 in q_n} G[d1][d] >= 2 )   <=>  0.25*s >= 0.5
__global__ void __launch_bounds__(256)
attn_kernel()
{
    __shared__ unsigned Ks[1024], Vs[1024];
    __shared__ int Gm[16][16];

    const int th  = blockIdx.x;      // t = th>>4, h = th&15
    const int tid = threadIdx.x;
    const int base = th << 10;

    for (int i = tid; i < 1024; i += 256) {
        Ks[i] = g_bits[1][base + i];
        Vs[i] = g_bits[2][base + i];
    }
    __syncthreads();

    // 256 threads == 16x16 (d1,d2) pairs
    {
        const int d1 = tid >> 4, d2 = tid & 15;
        int cnt = 0;
        #pragma unroll 8
        for (int n = 0; n < 1024; ++n)
            cnt += (int)((Ks[n] >> d1) & (Vs[n] >> d2) & 1u);
        Gm[d1][d2] = cnt;
    }
    __syncthreads();

    const int t = th >> 4, h = th & 15;
    for (int i = tid; i < 1024; i += 256) {
        unsigned q = g_bits[0][base + i];
        int acc[16] = {};
        unsigned qq = q;
        while (qq) {
            int d1 = __ffs(qq) - 1;
            qq &= qq - 1;
            #pragma unroll
            for (int d = 0; d < 16; ++d) acc[d] += Gm[d1][d];
        }
        #pragma unroll
        for (int d = 0; d < 16; ++d)
            g_s2[t * CN + (h * 16 + d) * N_ + i] = (acc[d] >= 2) ? 1.0f : 0.0f;
    }
}

// ---------------- final proj BN + spike (vth = 1.0) -> output ---------------
__global__ void __launch_bounds__(256)
final_kernel(const float* __restrict__ gp, const float* __restrict__ bp,
             float* __restrict__ out)
{
    const int idx = blockIdx.x * 256 + threadIdx.x;   // 0..TOT-1
    const int c = (idx >> 10) & 255;
    float xv = g_p[idx];
    float bn = gp[c] * (xv - g_mean[3 * C_ + c]) * g_istd[3 * C_ + c] + bp[c];
    out[idx] = (bn >= 1.0f) ? 1.0f : 0.0f;
}

// ---------------- launcher --------------------------------------------------
extern "C" void kernel_launch(void* const* d_in, const int* in_sizes, int n_in,
                              void* d_out, int out_size)
{
    const float* x  = (const float*)d_in[0];
    const float* y  = (const float*)d_in[1];
    const float* Wq = (const float*)d_in[2];
    const float* gq = (const float*)d_in[3];
    const float* bq = (const float*)d_in[4];
    const float* Wk = (const float*)d_in[5];
    const float* gk = (const float*)d_in[6];
    const float* bk = (const float*)d_in[7];
    const float* Wv = (const float*)d_in[8];
    const float* gv = (const float*)d_in[9];
    const float* bv = (const float*)d_in[10];
    const float* Wp = (const float*)d_in[11];
    const float* gp = (const float*)d_in[12];
    const float* bp = (const float*)d_in[13];
    float* out = (float*)d_out;

    gemm_branch<<<dim3(64, 4, 3), 256>>>(x, y, Wq, Wk, Wv);
    stats_kernel<<<dim3(C_, 3), 256>>>(0);
    pack_kernel<<<dim3(256, 3), 256>>>(gq, bq, gk, bk, gv, bv);
    attn_kernel<<<64, 256>>>();
    gemm_proj<<<dim3(64, 4, 1), 256>>>(Wp);
    stats_kernel<<<dim3(C_, 1), 256>>>(1);
    final_kernel<<<TOT / 256, 256>>>(gp, bp, out);
}

// round 5
// speedup vs baseline: 1.0899x; 1.0899x over previous
#include <cuda_runtime.h>

// Problem constants (T=4, B=1, C=256, N=1024, H=16, D=16)
#define T_   4
#define C_   256
#define N_   1024
#define M_   4          // T*B
#define H_   16
#define D_   16
#define CN   (C_*N_)    // 262144
#define TOT  (M_*C_*N_) // 1048576
#define EPSV 1e-5f

// ---------------- scratch (device globals; allocation-free) ----------------
__device__ float    g_h[3][TOT];      // q/k/v pre-BN activations (12 MiB)
__device__ float    g_p[TOT];         // proj pre-BN activations (4 MiB)
__device__ float    g_s2[TOT];        // attn-lif output as {0,1} fp32 (4 MiB)
__device__ float    g_mean[4*C_];     // per-channel mean  (z=0..2 branches, z=3 proj)
__device__ float    g_istd[4*C_];     // per-channel 1/sqrt(var+eps)
__device__ unsigned g_bits[3][M_*H_*N_]; // bitpacked spikes: mask over d at (t,h,n)
__device__ int      g_G[64*256];      // per-(t,h) 16x16 integer Gram matrix k^T v

// ---------------- f32x2 helpers (FFMA2: exact dual fp32 FMA) ----------------
__device__ __forceinline__ unsigned long long dup2(float v) {
    unsigned long long r; unsigned u = __float_as_uint(v);
    asm("mov.b64 %0, {%1, %1};" : "=l"(r) : "r"(u));
    return r;
}
#define FFMA2(acc, a, b) \
    asm("fma.rn.f32x2 %0, %1, %2, %0;" : "+l"(acc) : "l"(a), "l"(b))

// ---------------- GEMM body: O[m,o,n] = sum_c W[o,c] * X[m,c,n] -------------
// BM=64, BN=128, BK=16, 256 threads, 4x8 register tile per thread (f32x2).
__device__ __forceinline__ void gemm_body(const float* __restrict__ W,
                                          const float* __restrict__ X,
                                          float* __restrict__ O)
{
    __shared__ float As[16][68];    // [k][o], padded
    __shared__ float Bs[16][128];   // [k][n]

    const int tid     = threadIdx.x;
    const int colTile = blockIdx.x;          // 0..31  (4096 cols / 128)
    const int m       = colTile >> 3;        // 8 col tiles per m (1024/128)
    const int n0      = (colTile & 7) << 7;
    const int o0      = blockIdx.y << 6;     // 4 row tiles (C=256 / 64)
    const int ty      = tid >> 4;            // 0..15 -> 4 rows each
    const int tx      = tid & 15;            // 0..15 -> 8 cols each

    // loader indices
    const int lo_o = tid >> 2;               // As: 0..63
    const int lo_c = (tid & 3) << 2;         // As: 0,4,8,12
    const int lb_c = tid >> 4;               // Bs: 0..15
    const int lb_n = (tid & 15) << 3;        // Bs: 0..120 step 8

    unsigned long long acc[4][4];            // 4 rows x 4 f32x2 pairs (8 cols)
    #pragma unroll
    for (int i = 0; i < 4; ++i)
        #pragma unroll
        for (int j = 0; j < 4; ++j) acc[i][j] = 0ull;

    for (int k0 = 0; k0 < C_; k0 += 16) {
        // load W tile (transposed into As[k][o])
        {
            float4 wv = *(const float4*)&W[(o0 + lo_o) * C_ + k0 + lo_c];
            As[lo_c + 0][lo_o] = wv.x;
            As[lo_c + 1][lo_o] = wv.y;
            As[lo_c + 2][lo_o] = wv.z;
            As[lo_c + 3][lo_o] = wv.w;
        }
        // load X tile
        {
            const float* src = &X[m * CN + (k0 + lb_c) * N_ + n0 + lb_n];
            float4 x0 = *(const float4*)(src);
            float4 x1 = *(const float4*)(src + 4);
            *(float4*)&Bs[lb_c][lb_n]     = x0;
            *(float4*)&Bs[lb_c][lb_n + 4] = x1;
        }
        __syncthreads();

        #pragma unroll
        for (int k = 0; k < 16; ++k) {
            float4 av = *(const float4*)&As[k][ty * 4];
            unsigned long long ap[4];
            ap[0] = dup2(av.x); ap[1] = dup2(av.y);
            ap[2] = dup2(av.z); ap[3] = dup2(av.w);
            ulonglong2 b01 = *(const ulonglong2*)&Bs[k][tx * 8];
            ulonglong2 b23 = *(const ulonglong2*)&Bs[k][tx * 8 + 4];
            unsigned long long bp[4] = { b01.x, b01.y, b23.x, b23.y };
            #pragma unroll
            for (int i = 0; i < 4; ++i) {
                FFMA2(acc[i][0], ap[i], bp[0]);
                FFMA2(acc[i][1], ap[i], bp[1]);
                FFMA2(acc[i][2], ap[i], bp[2]);
                FFMA2(acc[i][3], ap[i], bp[3]);
            }
        }
        __syncthreads();
    }

    #pragma unroll
    for (int i = 0; i < 4; ++i) {
        float* dst = &O[m * CN + (o0 + ty * 4 + i) * N_ + n0 + tx * 8];
        ulonglong2 s0, s1;
        s0.x = acc[i][0]; s0.y = acc[i][1];
        s1.x = acc[i][2]; s1.y = acc[i][3];
        *(ulonglong2*)(dst)     = s0;
        *(ulonglong2*)(dst + 4) = s1;
    }
}

// Branch GEMMs: z=0 -> Wq@x, z=1 -> Wk@y, z=2 -> Wv@y
__global__ void __launch_bounds__(256)
gemm_branch(const float* __restrict__ x, const float* __restrict__ y,
            const float* __restrict__ Wq, const float* __restrict__ Wk,
            const float* __restrict__ Wv)
{
    const int z = blockIdx.z;
    const float* W = (z == 0) ? Wq : (z == 1) ? Wk : Wv;
    const float* X = (z == 0) ? x : y;
    gemm_body(W, X, g_h[z]);
}

// Proj GEMM: g_p = Wp @ g_s2
__global__ void __launch_bounds__(256)
gemm_proj(const float* __restrict__ Wp)
{
    gemm_body(Wp, g_s2, g_p);
}

// ---------------- per-channel BN stats over (m,n): 4096 samples -------------
__global__ void __launch_bounds__(256)
stats_kernel(int mode)
{
    const int c = blockIdx.x;
    const int z = blockIdx.y;
    const float* Hs;
    int sidx;
    if (mode == 0) { Hs = g_h[z]; sidx = z * C_ + c; }
    else           { Hs = g_p;    sidx = 3 * C_ + c; }

    const int tid = threadIdx.x;
    float s = 0.0f, q = 0.0f;
    #pragma unroll
    for (int j = 0; j < 16; ++j) {
        int idx = tid + j * 256;         // 0..4095
        int m = idx >> 10, n = idx & 1023;
        float v = Hs[m * CN + c * N_ + n];
        s += v;
        q += v * v;
    }
    #pragma unroll
    for (int off = 16; off > 0; off >>= 1) {
        s += __shfl_down_sync(0xFFFFFFFFu, s, off);
        q += __shfl_down_sync(0xFFFFFFFFu, q, off);
    }
    __shared__ float ss[8], qq[8];
    const int wid = tid >> 5, lane = tid & 31;
    if (lane == 0) { ss[wid] = s; qq[wid] = q; }
    __syncthreads();
    if (tid == 0) {
        float st = 0.0f, qt = 0.0f;
        #pragma unroll
        for (int w = 0; w < 8; ++w) { st += ss[w]; qt += qq[w]; }
        float mean = st * (1.0f / 4096.0f);
        float var  = qt * (1.0f / 4096.0f) - mean * mean;
        g_mean[sidx] = mean;
        g_istd[sidx] = rsqrtf(var + EPSV);
    }
}

// ---------------- BN + LIF spike + bitpack (vth = 1.0) ----------------------
__global__ void __launch_bounds__(256)
pack_kernel(const float* __restrict__ gq, const float* __restrict__ bq,
            const float* __restrict__ gk, const float* __restrict__ bk,
            const float* __restrict__ gv, const float* __restrict__ bv)
{
    const int z   = blockIdx.y;
    const int idx = blockIdx.x * 256 + threadIdx.x;  // (m,h,n), n fastest
    const int n = idx & 1023;
    const int h = (idx >> 10) & 15;
    const int m = idx >> 14;
    const float* G  = (z == 0) ? gq : (z == 1) ? gk : gv;
    const float* Bt = (z == 0) ? bq : (z == 1) ? bk : bv;
    const float* Hs = g_h[z];

    unsigned mask = 0;
    #pragma unroll
    for (int d = 0; d < 16; ++d) {
        int c = h * 16 + d;
        float xv = Hs[m * CN + c * N_ + n];
        float bn = G[c] * (xv - g_mean[z * C_ + c]) * g_istd[z * C_ + c] + Bt[c];
        if (bn >= 1.0f) mask |= (1u << d);
    }
    g_bits[z][idx] = mask;
}

// ---------------- attention phase 1: G[d1][d2] = sum_n k[n,d1]*v[n,d2] -------
// One block per (t,h). Bit-transpose via ballot, then 16x16 threads do
// 32x POPC(AND) each. Exact integers.
__global__ void __launch_bounds__(256)
attnA_kernel()
{
    __shared__ unsigned Ktr[16][33];   // [d][n-word], padded
    __shared__ unsigned Vtr[16][33];

    const int th   = blockIdx.x;       // (t,h)
    const int tid  = threadIdx.x;
    const int base = th << 10;
    const int warp = tid >> 5, lane = tid & 31;

    // each warp transposes 4 chunks of 32 n's
    #pragma unroll
    for (int cc = 0; cc < 4; ++cc) {
        const int chunk = warp * 4 + cc;            // 0..31
        const int n = chunk * 32 + lane;
        unsigned kw = g_bits[1][base + n];
        unsigned vw = g_bits[2][base + n];
        #pragma unroll
        for (int d = 0; d < 16; ++d) {
            unsigned km = __ballot_sync(0xFFFFFFFFu, (kw >> d) & 1u);
            unsigned vm = __ballot_sync(0xFFFFFFFFu, (vw >> d) & 1u);
            if (lane == d)      Ktr[d][chunk] = km;
            else if (lane == 16 + d) Vtr[d][chunk] = vm;
        }
        // lane==d wrote K, lane==16+d wrote V; but V for lane<16 not written.
        // Fix: redo V store properly below.
        if (lane < 16) { /* no-op */ }
    }
    __syncthreads();

    // safety: the ballot value is uniform across the warp; above we let lane d
    // store K and lane 16+d store V, covering all 16 d with lanes 0..31. OK.

    const int d1 = tid >> 4, d2 = tid & 15;
    int cnt = 0;
    #pragma unroll
    for (int w = 0; w < 32; ++w)
        cnt += __popc(Ktr[d1][w] & Vtr[d2][w]);
    g_G[th * 256 + tid] = cnt;
}

// ---------------- attention phase 2: s2[n,d] = (sum_{d1 in q_n} G[d1][d] >= 2)
// grid = 64 th * 4 n-chunks; one thread per n; branchless masked adds.
__global__ void __launch_bounds__(256)
attnB_kernel()
{
    __shared__ int Gs[256];
    const int bid   = blockIdx.x;
    const int th    = bid >> 2;
    const int chunk = bid & 3;
    const int tid   = threadIdx.x;
    const int n     = chunk * 256 + tid;

    Gs[tid] = g_G[th * 256 + tid];
    __syncthreads();

    const unsigned q = g_bits[0][(th << 10) + n];
    int acc[16];
    #pragma unroll
    for (int d = 0; d < 16; ++d) acc[d] = 0;

    #pragma unroll
    for (int d1 = 0; d1 < 16; ++d1) {
        const int msk = -(int)((q >> d1) & 1u);
        #pragma unroll
        for (int d = 0; d < 16; ++d)
            acc[d] += Gs[d1 * 16 + d] & msk;
    }

    const int t = th >> 4, h = th & 15;
    #pragma unroll
    for (int d = 0; d < 16; ++d)
        g_s2[t * CN + (h * 16 + d) * N_ + n] = (acc[d] >= 2) ? 1.0f : 0.0f;
}

// ---------------- final proj BN + spike (vth = 1.0) -> output ---------------
__global__ void __launch_bounds__(256)
final_kernel(const float* __restrict__ gp, const float* __restrict__ bp,
             float* __restrict__ out)
{
    const int idx = blockIdx.x * 256 + threadIdx.x;   // 0..TOT-1
    const int c = (idx >> 10) & 255;
    float xv = g_p[idx];
    float bn = gp[c] * (xv - g_mean[3 * C_ + c]) * g_istd[3 * C_ + c] + bp[c];
    out[idx] = (bn >= 1.0f) ? 1.0f : 0.0f;
}

// ---------------- launcher --------------------------------------------------
extern "C" void kernel_launch(void* const* d_in, const int* in_sizes, int n_in,
                              void* d_out, int out_size)
{
    const float* x  = (const float*)d_in[0];
    const float* y  = (const float*)d_in[1];
    const float* Wq = (const float*)d_in[2];
    const float* gq = (const float*)d_in[3];
    const float* bq = (const float*)d_in[4];
    const float* Wk = (const float*)d_in[5];
    const float* gk = (const float*)d_in[6];
    const float* bk = (const float*)d_in[7];
    const float* Wv = (const float*)d_in[8];
    const float* gv = (const float*)d_in[9];
    const float* bv = (const float*)d_in[10];
    const float* Wp = (const float*)d_in[11];
    const float* gp = (const float*)d_in[12];
    const float* bp = (const float*)d_in[13];
    float* out = (float*)d_out;

    gemm_branch<<<dim3(32, 4, 3), 256>>>(x, y, Wq, Wk, Wv);
    stats_kernel<<<dim3(C_, 3), 256>>>(0);
    pack_kernel<<<dim3(256, 3), 256>>>(gq, bq, gk, bk, gv, bv);
    attnA_kernel<<<64, 256>>>();
    attnB_kernel<<<256, 256>>>();
    gemm_proj<<<dim3(32, 4, 1), 256>>>(Wp);
    stats_kernel<<<dim3(C_, 1), 256>>>(1);
    final_kernel<<<TOT / 256, 256>>>(gp, bp, out);
}